// round 4
// baseline (speedup 1.0000x reference)
#include <cuda_runtime.h>
#include <cuda_bf16.h>
#include <math.h>

// Problem dims (fixed by the dataset)
#define B_   512
#define T1_  64
#define E_   50
#define H_   32
#define N_   32768
#define T2_  32
#define DN_  49
#define FCIN_ 305
#define HID_ 32

#define POS_INF_F (__int_as_float(0x7f800000))

// Scratch (static device globals — no runtime allocation)
__device__ float g_h2[(size_t)N_ * 64];     // [N, 2H] timeline RNN final hidden
__device__ float g_hn[(size_t)B_ * 64];     // [B, 2H] text RNN final hidden
__device__ float g_red[(size_t)B_ * 192];   // [B, mean(64)|min(64)|max(64)]

__device__ __forceinline__ float tanh_fast(float x) {
    float ax = fabsf(x);
    float e  = __expf(-2.0f * ax);
    float r  = __fdividef(1.0f - e, 1.0f + e);
    return copysignf(r, x);
}

// ---------------------------------------------------------------------------
// Fused RNN kernel.
//  blocks [0, 8):    rnn1 over text_features      (512 seqs, T=64, 2 dirs)
//  blocks [8, 520):  rnn2 over timeline features  (32768 seqs, T=32, 2 dirs)
// Each block: 128 threads = 128 sequences, one direction.
// Thread keeps h[32] and acc[32] in registers; weights broadcast from smem.
// ---------------------------------------------------------------------------
__global__ void __launch_bounds__(128) rnn_kernel(
    const float* __restrict__ text,      // [512, 64, 50]
    const float* __restrict__ timeline,  // [32768, 32, 50]
    const float* __restrict__ r1_wif, const float* __restrict__ r1_whf,
    const float* __restrict__ r1_bif, const float* __restrict__ r1_bhf,
    const float* __restrict__ r1_wib, const float* __restrict__ r1_whb,
    const float* __restrict__ r1_bib, const float* __restrict__ r1_bhb,
    const float* __restrict__ r2_wif, const float* __restrict__ r2_whf,
    const float* __restrict__ r2_bif, const float* __restrict__ r2_bhf,
    const float* __restrict__ r2_wib, const float* __restrict__ r2_whb,
    const float* __restrict__ r2_bib, const float* __restrict__ r2_bhb)
{
    __shared__ __align__(16) float sWihT[E_ * H_];   // [e][i]
    __shared__ __align__(16) float sWhhT[H_ * H_];   // [j][i]
    __shared__ __align__(16) float sB[H_];
    __shared__ float sX[128 * 51];                   // x slice, pad 51 (conflict-free)

    const int tid = threadIdx.x;
    const int blk = blockIdx.x;

    const float* X; const float* wih; const float* whh;
    const float* bih; const float* bhh;
    float* dst; int T, seq0, dir;

    if (blk < 8) {
        const int b1 = blk; dir = b1 & 1; const int grp = b1 >> 1;
        T = T1_; X = text; seq0 = grp * 128; dst = g_hn;
        if (dir == 0) { wih = r1_wif; whh = r1_whf; bih = r1_bif; bhh = r1_bhf; }
        else          { wih = r1_wib; whh = r1_whb; bih = r1_bib; bhh = r1_bhb; }
    } else {
        const int b2 = blk - 8; dir = b2 & 1; const int grp = b2 >> 1;
        T = T2_; X = timeline; seq0 = grp * 128; dst = g_h2;
        if (dir == 0) { wih = r2_wif; whh = r2_whf; bih = r2_bif; bhh = r2_bhf; }
        else          { wih = r2_wib; whh = r2_whb; bih = r2_bib; bhh = r2_bhb; }
    }

    // Stage weights transposed into shared.
    for (int idx = tid; idx < E_ * H_; idx += 128) {
        int i = idx / E_, e = idx - i * E_;
        sWihT[e * H_ + i] = wih[idx];
    }
    for (int idx = tid; idx < H_ * H_; idx += 128) {
        int i = idx >> 5, j = idx & 31;
        sWhhT[j * H_ + i] = whh[idx];
    }
    if (tid < H_) sB[tid] = bih[tid] + bhh[tid];

    float h[H_];
#pragma unroll
    for (int i = 0; i < H_; i++) h[i] = 0.0f;

    const size_t seq_stride = (size_t)T * E_;
    const float* Xbase = X + (size_t)seq0 * seq_stride;
    const float* xrow = &sX[tid * 51];

    for (int t = 0; t < T; t++) {
        const int teff = dir ? (T - 1 - t) : t;
        __syncthreads();   // covers weight staging on t==0; sX reuse on t>0
        // Cooperative coalesced load of X[seq0:seq0+128, teff, :]
        {
            const float* src = Xbase + (size_t)teff * E_;
            for (int j = tid; j < 128 * E_; j += 128) {
                int s = j / E_, e = j - s * E_;
                sX[s * 51 + e] = src[(size_t)s * seq_stride + e];
            }
        }
        __syncthreads();

        float acc[H_];
        {
            const float4* b4 = reinterpret_cast<const float4*>(sB);
#pragma unroll
            for (int q = 0; q < 8; q++) {
                float4 b = b4[q];
                acc[4*q+0] = b.x; acc[4*q+1] = b.y; acc[4*q+2] = b.z; acc[4*q+3] = b.w;
            }
        }
        // x @ W_ih^T
        for (int e = 0; e < E_; e++) {
            float xe = xrow[e];
            const float4* w4 = reinterpret_cast<const float4*>(&sWihT[e * H_]);
#pragma unroll
            for (int q = 0; q < 8; q++) {
                float4 w = w4[q];
                acc[4*q+0] = fmaf(w.x, xe, acc[4*q+0]);
                acc[4*q+1] = fmaf(w.y, xe, acc[4*q+1]);
                acc[4*q+2] = fmaf(w.z, xe, acc[4*q+2]);
                acc[4*q+3] = fmaf(w.w, xe, acc[4*q+3]);
            }
        }
        // h @ W_hh^T   (j fully unrolled so h[] stays in registers)
#pragma unroll
        for (int j = 0; j < H_; j++) {
            float hj = h[j];
            const float4* w4 = reinterpret_cast<const float4*>(&sWhhT[j * H_]);
#pragma unroll
            for (int q = 0; q < 8; q++) {
                float4 w = w4[q];
                acc[4*q+0] = fmaf(w.x, hj, acc[4*q+0]);
                acc[4*q+1] = fmaf(w.y, hj, acc[4*q+1]);
                acc[4*q+2] = fmaf(w.z, hj, acc[4*q+2]);
                acc[4*q+3] = fmaf(w.w, hj, acc[4*q+3]);
            }
        }
#pragma unroll
        for (int i = 0; i < H_; i++) h[i] = tanh_fast(acc[i]);
    }

    // Write final hidden: dst[seq][dir*32 + i]
    float* o = dst + (size_t)(seq0 + tid) * 64 + dir * 32;
#pragma unroll
    for (int i = 0; i < H_; i++) o[i] = h[i];
}

// ---------------------------------------------------------------------------
// Ragged segment mean/min/max of g_h2 over timeline_elements.
// One block per batch row, 64 threads (one per feature).
// Indices clamped defensively: even if te were misresolved, we never read
// outside g_h2 (turns a crash into a diagnosable numeric mismatch).
// ---------------------------------------------------------------------------
__global__ void reduce_kernel(const int* __restrict__ te)
{
    const int b = blockIdx.x;
    const int f = threadIdx.x;

    long long start = 0;
    for (int k = 0; k < b; k++) start += te[k];
    if (start < 0) start = 0;
    if (start > N_) start = N_;
    int cnt = te[b];
    if (cnt < 1) cnt = 1;
    if (start + cnt > N_) cnt = (int)(N_ - start);
    if (cnt < 1) cnt = 1;

    const float* p = g_h2 + (size_t)start * 64 + f;
    float s = 0.0f, mn = POS_INF_F, mx = -POS_INF_F;
    for (int r = 0; r < cnt; r++) {
        float v = p[(size_t)r * 64];
        s += v; mn = fminf(mn, v); mx = fmaxf(mx, v);
    }
    float* o = g_red + (size_t)b * 192;
    o[f]        = s / (float)cnt;
    o[64 + f]   = mn;
    o[128 + f]  = mx;
}

// ---------------------------------------------------------------------------
// fc1 (305->32) tanh, fc2 (32->1) sigmoid. One warp per batch row.
// ---------------------------------------------------------------------------
__global__ void fc_kernel(const float* __restrict__ normal,
                          const float* __restrict__ fc1_w,
                          const float* __restrict__ fc1_b,
                          const float* __restrict__ fc2_w,
                          const float* __restrict__ fc2_b,
                          float* __restrict__ out)
{
    const int b = blockIdx.x;
    const int i = threadIdx.x;   // 32
    __shared__ float x[FCIN_];

    for (int k = i; k < FCIN_; k += 32) {
        float v;
        if (k < 64)        v = g_hn[(size_t)b * 64 + k];
        else if (k < 113)  v = normal[(size_t)b * DN_ + (k - 64)];
        else               v = g_red[(size_t)b * 192 + (k - 113)];
        x[k] = v;
    }
    __syncwarp();

    float a = fc1_b[i];
    const float* w = fc1_w + (size_t)i * FCIN_;
    for (int k = 0; k < FCIN_; k++) a = fmaf(w[k], x[k], a);
    float y = tanh_fast(a);
    float z = y * fc2_w[i];
#pragma unroll
    for (int off = 16; off > 0; off >>= 1)
        z += __shfl_xor_sync(0xffffffffu, z, off);
    if (i == 0)
        out[b] = 1.0f / (1.0f + __expf(-(z + fc2_b[0])));
}

extern "C" void kernel_launch(void* const* d_in, const int* in_sizes, int n_in,
                              void* d_out, int out_size)
{
    // Resolve input ordering: setup_inputs dict order has timeline_elements (512
    // int32) at index 3; reference-signature order has it last.
    int wbase; const int* te;
    if (in_sizes[3] == B_) { wbase = 4;  te = (const int*)d_in[3]; }
    else                   { wbase = 3;  te = (const int*)d_in[n_in - 1]; }

    const float* normal   = (const float*)d_in[0];
    const float* text     = (const float*)d_in[1];
    const float* timeline = (const float*)d_in[2];

    const float* w[16];
    for (int k = 0; k < 16; k++) w[k] = (const float*)d_in[wbase + k];
    const float* fc1_w = (const float*)d_in[wbase + 16];
    const float* fc1_b = (const float*)d_in[wbase + 17];
    const float* fc2_w = (const float*)d_in[wbase + 18];
    const float* fc2_b = (const float*)d_in[wbase + 19];

    rnn_kernel<<<8 + (N_ / 128) * 2, 128>>>(
        text, timeline,
        w[0], w[1], w[2], w[3], w[4], w[5], w[6], w[7],
        w[8], w[9], w[10], w[11], w[12], w[13], w[14], w[15]);

    reduce_kernel<<<B_, 64>>>(te);

    fc_kernel<<<B_, 32>>>(normal, fc1_w, fc1_b, fc2_w, fc2_b, (float*)d_out);
}